// round 7
// baseline (speedup 1.0000x reference)
#include <cuda_runtime.h>
#include <cuda_fp16.h>
#include <cstdint>
#include <cstddef>

#define D 128
#define MAXN 50000
#define MAXE 800000
#define BN_EPS 1e-5f
#define SCAN_B 1024
#define NBLK ((MAXN + SCAN_B - 1) / SCAN_B)   // 49
#define TGRID 296                              // 2 persistent CTAs per SM

// ---------------- device scratch ----------------
__device__ __half2 g_x16[(size_t)MAXN * 64];    // fp16 x
__device__ __half2 g_h16[(size_t)MAXN * 64];    // fp16 h (later relu(bn(h)) in place)
__device__ __half2 g_agg16[(size_t)MAXN * 64];  // fp16 neighbor mean
__device__ __half2 g_bf1[16 * 16 * 32 * 2];     // layer-1 B fragments (fragment-ordered)
__device__ __half2 g_bf2[16 * 16 * 32 * 2];     // layer-2 B fragments
__device__ int    g_cnt[MAXN];
__device__ int    g_offs[MAXN + 1];
__device__ int    g_cur[MAXN];
__device__ int    g_bsum[NBLK];
__device__ int    g_esrc[MAXE];
__device__ float  g_colsum[D], g_colsumsq[D], g_scale[D], g_shift[D];

// ---------------- helpers ----------------
__device__ __forceinline__ void red_add1(float* p, float v) {
    asm volatile("red.global.add.f32 [%0], %1;" :: "l"(p), "f"(v) : "memory");
}
__device__ __forceinline__ void mma16816(float* c, uint32_t a0, uint32_t a1,
                                         uint32_t a2, uint32_t a3,
                                         uint32_t b0, uint32_t b1) {
    asm volatile("mma.sync.aligned.m16n8k16.row.col.f32.f16.f16.f32 "
                 "{%0,%1,%2,%3}, {%4,%5,%6,%7}, {%8,%9}, {%0,%1,%2,%3};"
                 : "+f"(c[0]), "+f"(c[1]), "+f"(c[2]), "+f"(c[3])
                 : "r"(a0), "r"(a1), "r"(a2), "r"(a3), "r"(b0), "r"(b1));
}

// ---------------- fp32 -> fp16 conversion of x ----------------
__global__ void conv_half_k(const float* __restrict__ x, int n4) {
    int i = blockIdx.x * blockDim.x + threadIdx.x;
    if (i >= n4) return;
    float4 v = __ldg((const float4*)x + i);
    g_x16[(size_t)i * 2]     = __floats2half2_rn(v.x, v.y);
    g_x16[(size_t)i * 2 + 1] = __floats2half2_rn(v.z, v.w);
}

// ---------------- B fragment precompute (both layers) ----------------
__global__ void prep_bfrag_k(const float* __restrict__ w1l, const float* __restrict__ w1r,
                             const float* __restrict__ w2l, const float* __restrict__ w2r) {
    int idx = blockIdx.x * blockDim.x + threadIdx.x;   // 0..16383
    if (idx >= 16384) return;
    int layer = idx >> 13;
    int slot  = idx & 8191;          // (ks*16+nt)*32 + lane
    int lane  = slot & 31;
    int fk    = slot >> 5;
    int ks = fk >> 4, nt = fk & 15;
    int n  = nt * 8 + (lane >> 2);
    int k0 = ks * 16 + 2 * (lane & 3);
    const float* wl = layer ? w2l : w1l;
    const float* wr = layer ? w2r : w1r;
    auto W = [&](int k) { return (k < 128) ? wl[n * 128 + k] : wr[n * 128 + k - 128]; };
    __half2* dst = (layer ? g_bf2 : g_bf1) + (size_t)slot * 2;
    dst[0] = __floats2half2_rn(W(k0),     W(k0 + 1));
    dst[1] = __floats2half2_rn(W(k0 + 8), W(k0 + 9));
}

// ---------------- CSR build ----------------
__global__ void hist_k(const int* __restrict__ ei, int E) {
    int e = blockIdx.x * blockDim.x + threadIdx.x;
    if (e < E) atomicAdd(&g_cnt[ei[E + e]], 1);
}

__global__ void scan_local_k(int n) {
    __shared__ int sm[SCAN_B];
    int t = threadIdx.x, i = blockIdx.x * SCAN_B + t;
    int v = (i < n) ? g_cnt[i] : 0;
    sm[t] = v; __syncthreads();
    int acc = v;
    #pragma unroll
    for (int off = 1; off < SCAN_B; off <<= 1) {
        int add = (t >= off) ? sm[t - off] : 0;
        __syncthreads();
        acc += add; sm[t] = acc;
        __syncthreads();
    }
    if (i < n) g_offs[i] = acc - v;
    if (t == SCAN_B - 1) g_bsum[blockIdx.x] = acc;
}

// scan_add with the 49-entry block-sum scan done redundantly per block (one launch fewer)
__global__ void scan_add_k(int n, int E) {
    __shared__ int sb[64];
    int t = threadIdx.x;
    int orig = 0;
    if (t < 64) { orig = (t < NBLK) ? g_bsum[t] : 0; sb[t] = orig; }
    __syncthreads();
    #pragma unroll
    for (int off = 1; off < 64; off <<= 1) {
        int add = 0;
        if (t < 64 && t >= off) add = sb[t - off];
        __syncthreads();
        if (t < 64) sb[t] += add;
        __syncthreads();
    }
    if (t < 64) sb[t] -= orig;        // inclusive -> exclusive
    __syncthreads();
    int i = blockIdx.x * blockDim.x + t;
    if (i < n) {
        int o = g_offs[i] + sb[i >> 10];    // SCAN_B = 1024
        g_offs[i] = o;
        g_cur[i] = o;
    }
    if (i == n) g_offs[n] = E;
}

__global__ void fill_k(const int* __restrict__ ei, int E) {
    int e = blockIdx.x * blockDim.x + threadIdx.x;
    if (e < E) {
        int d = ei[E + e];
        int pos = atomicAdd(&g_cur[d], 1);
        g_esrc[pos] = ei[e];
    }
}

// ---------------- gather v3: one warp per node, half-warp per edge, LDG.128 ------
// lane = (sub<<4) | c16 : sub-half handles edges e = s0+sub, s0+sub+2, ...
// c16 owns cols c16*8 .. c16*8+7 (one uint4 = 8 halves). fp32 accumulate,
// shfl.xor(16) butterfly merges the two half-warps. Exact same math as v2.
__global__ void gather_k(const __half2* __restrict__ feat, int N) {
    int gw = (blockIdx.x * blockDim.x + threadIdx.x) >> 5;
    int lane = threadIdx.x & 31;
    if (gw >= N) return;
    int s0 = g_offs[gw], s1 = g_offs[gw + 1];
    int sub = lane >> 4, c16 = lane & 15;
    const uint4* f = (const uint4*)feat;            // 16 uint4 per row
    float a0 = 0.f, a1 = 0.f, a2 = 0.f, a3 = 0.f;
    float a4 = 0.f, a5 = 0.f, a6 = 0.f, a7 = 0.f;
    for (int e = s0 + sub; e < s1; e += 2) {
        int s = __ldg(g_esrc + e);
        uint4 v = __ldg(f + (size_t)s * 16 + c16);
        float2 f0 = __half22float2(*(__half2*)&v.x);
        float2 f1 = __half22float2(*(__half2*)&v.y);
        float2 f2 = __half22float2(*(__half2*)&v.z);
        float2 f3 = __half22float2(*(__half2*)&v.w);
        a0 += f0.x; a1 += f0.y; a2 += f1.x; a3 += f1.y;
        a4 += f2.x; a5 += f2.y; a6 += f3.x; a7 += f3.y;
    }
    __syncwarp();
    a0 += __shfl_xor_sync(0xffffffffu, a0, 16);
    a1 += __shfl_xor_sync(0xffffffffu, a1, 16);
    a2 += __shfl_xor_sync(0xffffffffu, a2, 16);
    a3 += __shfl_xor_sync(0xffffffffu, a3, 16);
    a4 += __shfl_xor_sync(0xffffffffu, a4, 16);
    a5 += __shfl_xor_sync(0xffffffffu, a5, 16);
    a6 += __shfl_xor_sync(0xffffffffu, a6, 16);
    a7 += __shfl_xor_sync(0xffffffffu, a7, 16);
    if (sub == 0) {
        float inv = 1.0f / fmaxf((float)(s1 - s0), 1.0f);
        uint4 o;
        *(__half2*)&o.x = __floats2half2_rn(a0 * inv, a1 * inv);
        *(__half2*)&o.y = __floats2half2_rn(a2 * inv, a3 * inv);
        *(__half2*)&o.z = __floats2half2_rn(a4 * inv, a5 * inv);
        *(__half2*)&o.w = __floats2half2_rn(a6 * inv, a7 * inv);
        ((uint4*)g_agg16)[(size_t)gw * 16 + c16] = o;
    }
}

// ---------------- HMMA node transform ----------------
template<bool OUT_HALF>
__global__ void __launch_bounds__(256, 2)
mma_transform_k(const uint32_t* __restrict__ aggH,   // [m][64] half2-as-u32
                const uint32_t* __restrict__ selfH,
                const uint2* __restrict__ bfrag,     // 8192 x 8B fragments
                const float* __restrict__ bias,
                float* __restrict__ outF, __half2* __restrict__ outH,
                int nNodes, int ntiles) {
    extern __shared__ char smraw[];
    uint2* sB = (uint2*)smraw;                        // 64KB
    float* sBias = (float*)(smraw + 65536);
    int tid = threadIdx.x;
    for (int i = tid; i < 8192; i += 256) sB[i] = __ldg(bfrag + i);
    if (tid < 128) sBias[tid] = __ldg(bias + tid);
    __syncthreads();

    int warp = tid >> 5, lane = tid & 31;
    int r = lane >> 2, c = lane & 3;

    for (int tile = blockIdx.x; tile < ntiles; tile += gridDim.x) {
        int m0 = tile * 128 + warp * 16;
        size_t row0 = (size_t)min(m0 + r,     nNodes - 1);
        size_t row1 = (size_t)min(m0 + r + 8, nNodes - 1);
        const uint32_t* p0a = aggH  + row0 * 64 + c;
        const uint32_t* p1a = aggH  + row1 * 64 + c;
        const uint32_t* p0s = selfH + row0 * 64 + c;
        const uint32_t* p1s = selfH + row1 * 64 + c;

        float acc[16][4];
        #pragma unroll
        for (int nt = 0; nt < 16; nt++)
            #pragma unroll
            for (int q = 0; q < 4; q++) acc[nt][q] = 0.f;

        #pragma unroll
        for (int ks = 0; ks < 16; ks++) {
            const uint32_t* p0 = (ks < 8) ? p0a + ks * 8 : p0s + (ks - 8) * 8;
            const uint32_t* p1 = (ks < 8) ? p1a + ks * 8 : p1s + (ks - 8) * 8;
            uint32_t a0 = __ldg(p0), a2 = __ldg(p0 + 4);
            uint32_t a1 = __ldg(p1), a3 = __ldg(p1 + 4);
            const uint2* bp = sB + ks * 512 + lane;
            #pragma unroll
            for (int nt = 0; nt < 16; nt++) {
                uint2 b = bp[nt * 32];
                mma16816(acc[nt], a0, a1, a2, a3, b.x, b.y);
            }
        }

        bool ok0 = (m0 + r)     < nNodes;
        bool ok1 = (m0 + r + 8) < nNodes;
        #pragma unroll
        for (int nt = 0; nt < 16; nt++) {
            int j = nt * 8 + 2 * c;
            float b0 = sBias[j], b1 = sBias[j + 1];
            float v0 = acc[nt][0] + b0, v1 = acc[nt][1] + b1;
            float v2 = acc[nt][2] + b0, v3 = acc[nt][3] + b1;
            if (OUT_HALF) {
                if (ok0) outH[(size_t)(m0 + r)     * 64 + (j >> 1)] = __floats2half2_rn(v0, v1);
                if (ok1) outH[(size_t)(m0 + r + 8) * 64 + (j >> 1)] = __floats2half2_rn(v2, v3);
            } else {
                if (ok0) *(float2*)(outF + (size_t)(m0 + r)     * 128 + j) = make_float2(v0, v1);
                if (ok1) *(float2*)(outF + (size_t)(m0 + r + 8) * 128 + j) = make_float2(v2, v3);
            }
        }
    }
}

// ---------------- BN column stats over fp16 h ----------------
__global__ void stats_half_k(int N) {
    int c2  = threadIdx.x & 63;
    int sub = threadIdx.x >> 6;      // 0..3
    float sx = 0.f, sy = 0.f, qx = 0.f, qy = 0.f;
    for (int row = blockIdx.x * 4 + sub; row < N; row += gridDim.x * 4) {
        float2 f = __half22float2(g_h16[(size_t)row * 64 + c2]);
        sx += f.x; sy += f.y; qx += f.x * f.x; qy += f.y * f.y;
    }
    red_add1(g_colsum   + 2 * c2,     sx);
    red_add1(g_colsum   + 2 * c2 + 1, sy);
    red_add1(g_colsumsq + 2 * c2,     qx);
    red_add1(g_colsumsq + 2 * c2 + 1, qy);
}

// ---------------- BN finalize ----------------
__global__ void bn_finalize_k(const float* __restrict__ gamma,
                              const float* __restrict__ beta, float invN) {
    int j = threadIdx.x;
    float mu  = g_colsum[j] * invN;
    float var = g_colsumsq[j] * invN - mu * mu;
    float sc  = gamma[j] * rsqrtf(var + BN_EPS);
    g_scale[j] = sc;
    g_shift[j] = fmaf(-mu, sc, beta[j]);
}

// ---------------- relu(bn(h)) in place on fp16 h ----------------
__global__ void relu_bn_k(int total2) {
    int i = blockIdx.x * blockDim.x + threadIdx.x;
    if (i >= total2) return;
    int c2 = i & 63;
    float2 sc = ((const float2*)g_scale)[c2];
    float2 sh = ((const float2*)g_shift)[c2];
    float2 f = __half22float2(g_h16[i]);
    f.x = fmaxf(fmaf(f.x, sc.x, sh.x), 0.f);
    f.y = fmaxf(fmaf(f.y, sc.y, sh.y), 0.f);
    g_h16[i] = __floats2half2_rn(f.x, f.y);
}

// ---------------- launch ----------------
extern "C" void kernel_launch(void* const* d_in, const int* in_sizes, int n_in,
                              void* d_out, int out_size) {
    const float* x     = (const float*)d_in[0];
    const int*   ei    = (const int*)d_in[1];     // int32
    const float* w1l   = (const float*)d_in[2];
    const float* b1l   = (const float*)d_in[3];
    const float* w1r   = (const float*)d_in[4];
    const float* w2l   = (const float*)d_in[5];
    const float* b2l   = (const float*)d_in[6];
    const float* w2r   = (const float*)d_in[7];
    const float* gamma = (const float*)d_in[8];
    const float* beta  = (const float*)d_in[9];
    float*       out   = (float*)d_out;

    int N = in_sizes[0] / D;
    int E = in_sizes[1] / 2;
    int ntiles = (N + 127) / 128;

    void *p_cnt, *p_cs, *p_cq, *p_x16, *p_h16, *p_agg16, *p_bf1, *p_bf2;
    cudaGetSymbolAddress(&p_cnt,   g_cnt);
    cudaGetSymbolAddress(&p_cs,    g_colsum);
    cudaGetSymbolAddress(&p_cq,    g_colsumsq);
    cudaGetSymbolAddress(&p_x16,   g_x16);
    cudaGetSymbolAddress(&p_h16,   g_h16);
    cudaGetSymbolAddress(&p_agg16, g_agg16);
    cudaGetSymbolAddress(&p_bf1,   g_bf1);
    cudaGetSymbolAddress(&p_bf2,   g_bf2);

    int smem = 65536 + 512;
    cudaFuncSetAttribute(mma_transform_k<true>,
                         cudaFuncAttributeMaxDynamicSharedMemorySize, smem);
    cudaFuncSetAttribute(mma_transform_k<false>,
                         cudaFuncAttributeMaxDynamicSharedMemorySize, smem);

    cudaMemsetAsync(p_cnt, 0, (size_t)N * sizeof(int));
    cudaMemsetAsync(p_cs,  0, D * sizeof(float));
    cudaMemsetAsync(p_cq,  0, D * sizeof(float));

    conv_half_k<<<(N * 32 + 255) / 256, 256>>>(x, N * 32);
    prep_bfrag_k<<<64, 256>>>(w1l, w1r, w2l, w2r);

    // CSR build (reused by both layers)
    int egrid = (E + 255) / 256;
    hist_k<<<egrid, 256>>>(ei, E);
    scan_local_k<<<(N + SCAN_B - 1) / SCAN_B, SCAN_B>>>(N);
    scan_add_k<<<(N + 256) / 256, 256>>>(N, E);
    fill_k<<<egrid, 256>>>(ei, E);

    int ggrid = (N * 32 + 255) / 256;

    // layer 1: h = mean(x_nbr)@W1l + b1 + x@W1r   (fp16 inputs, fp32 acc)
    gather_k<<<ggrid, 256>>>((const __half2*)p_x16, N);
    mma_transform_k<true><<<TGRID, 256, smem>>>(
        (const uint32_t*)p_agg16, (const uint32_t*)p_x16,
        (const uint2*)p_bf1, b1l, nullptr, (__half2*)p_h16, N, ntiles);

    // BN
    stats_half_k<<<148, 256>>>(N);
    bn_finalize_k<<<1, D>>>(gamma, beta, 1.0f / (float)N);
    relu_bn_k<<<(N * 64 + 255) / 256, 256>>>(N * 64);

    // layer 2: out = mean(rbh_nbr)@W2l + b2 + rbh@W2r
    gather_k<<<ggrid, 256>>>((const __half2*)p_h16, N);
    mma_transform_k<false><<<TGRID, 256, smem>>>(
        (const uint32_t*)p_agg16, (const uint32_t*)p_h16,
        (const uint2*)p_bf2, b2l, out, nullptr, N, ntiles);
}

// round 8
// speedup vs baseline: 1.0724x; 1.0724x over previous
#include <cuda_runtime.h>
#include <cuda_fp16.h>
#include <cstdint>
#include <cstddef>

#define D 128
#define MAXN 50000
#define MAXE 800000
#define BN_EPS 1e-5f
#define SCAN_B 1024
#define NBLK ((MAXN + SCAN_B - 1) / SCAN_B)   // 49
#define TGRID 296                              // 2 persistent CTAs per SM

// ---------------- device scratch ----------------
__device__ __half2 g_x16[(size_t)MAXN * 64];    // fp16 x
__device__ __half2 g_h16[(size_t)MAXN * 64];    // fp16 h (relu(bn(h)) in place later)
__device__ __half2 g_agg16[(size_t)MAXN * 64];  // fp16 neighbor mean
__device__ __half2 g_bf1[16 * 16 * 32 * 2];     // layer-1 B fragments
__device__ __half2 g_bf2[16 * 16 * 32 * 2];     // layer-2 B fragments
__device__ int    g_cnt[MAXN];
__device__ int    g_offs[MAXN + 1];
__device__ int    g_cur[MAXN];
__device__ int    g_bsum[NBLK];
__device__ int    g_esrc[MAXE];
__device__ int    g_done;
__device__ float  g_colsum[D], g_colsumsq[D], g_scale[D], g_shift[D];

// ---------------- helpers ----------------
__device__ __forceinline__ void red_add1(float* p, float v) {
    asm volatile("red.global.add.f32 [%0], %1;" :: "l"(p), "f"(v) : "memory");
}
__device__ __forceinline__ void mma16816(float* c, uint32_t a0, uint32_t a1,
                                         uint32_t a2, uint32_t a3,
                                         uint32_t b0, uint32_t b1) {
    asm volatile("mma.sync.aligned.m16n8k16.row.col.f32.f16.f16.f32 "
                 "{%0,%1,%2,%3}, {%4,%5,%6,%7}, {%8,%9}, {%0,%1,%2,%3};"
                 : "+f"(c[0]), "+f"(c[1]), "+f"(c[2]), "+f"(c[3])
                 : "r"(a0), "r"(a1), "r"(a2), "r"(a3), "r"(b0), "r"(b1));
}

// ---------------- fused setup: zero scratch + conv x->fp16 + B fragments ---------
// block partition: [0, zb) zero | [zb, zb+64) bfrag | [zb+64, ...) conv
__global__ void setup_k(const float* __restrict__ x,
                        const float* __restrict__ w1l, const float* __restrict__ w1r,
                        const float* __restrict__ w2l, const float* __restrict__ w2r,
                        int N, int zb) {
    int b = blockIdx.x, t = threadIdx.x;
    if (b < zb) {
        int i = b * 256 + t;
        if (i < N) g_cnt[i] = 0;
        else if (i < N + 128) g_colsum[i - N] = 0.f;
        else if (i < N + 256) g_colsumsq[i - N - 128] = 0.f;
        else if (i == N + 256) g_done = 0;
        return;
    }
    if (b < zb + 64) {
        // B fragment precompute: m16n8k16 B frag, lane t%32 holds
        // {B[k0+2(t%4)][n], B[k0+2(t%4)+1][n]} and same at k+8; n = nt*8 + t/4
        int idx = (b - zb) * 256 + t;        // 0..16383
        int layer = idx >> 13;
        int slot  = idx & 8191;              // (ks*16+nt)*32 + lane
        int lane  = slot & 31;
        int fk    = slot >> 5;
        int ks = fk >> 4, nt = fk & 15;
        int n  = nt * 8 + (lane >> 2);
        int k0 = ks * 16 + 2 * (lane & 3);
        const float* wl = layer ? w2l : w1l;
        const float* wr = layer ? w2r : w1r;
        auto W = [&](int k) { return (k < 128) ? wl[n * 128 + k] : wr[n * 128 + k - 128]; };
        __half2* dst = (layer ? g_bf2 : g_bf1) + (size_t)slot * 2;
        dst[0] = __floats2half2_rn(W(k0),     W(k0 + 1));
        dst[1] = __floats2half2_rn(W(k0 + 8), W(k0 + 9));
        return;
    }
    int i = (b - zb - 64) * 256 + t;         // float4 index over x
    if (i >= N * 32) return;
    float4 v = __ldg((const float4*)x + i);
    g_x16[(size_t)i * 2]     = __floats2half2_rn(v.x, v.y);
    g_x16[(size_t)i * 2 + 1] = __floats2half2_rn(v.z, v.w);
}

// ---------------- CSR build ----------------
__global__ void hist_k(const int* __restrict__ ei, int E) {
    int e = blockIdx.x * blockDim.x + threadIdx.x;
    if (e < E) atomicAdd(&g_cnt[ei[E + e]], 1);
}

__global__ void scan_local_k(int n) {
    __shared__ int sm[SCAN_B];
    int t = threadIdx.x, i = blockIdx.x * SCAN_B + t;
    int v = (i < n) ? g_cnt[i] : 0;
    sm[t] = v; __syncthreads();
    int acc = v;
    #pragma unroll
    for (int off = 1; off < SCAN_B; off <<= 1) {
        int add = (t >= off) ? sm[t - off] : 0;
        __syncthreads();
        acc += add; sm[t] = acc;
        __syncthreads();
    }
    if (i < n) g_offs[i] = acc - v;
    if (t == SCAN_B - 1) g_bsum[blockIdx.x] = acc;
}

// scan_add with the 49-entry block-sum scan done redundantly per block
__global__ void scan_add_k(int n, int E) {
    __shared__ int sb[64];
    int t = threadIdx.x;
    int orig = 0;
    if (t < 64) { orig = (t < NBLK) ? g_bsum[t] : 0; sb[t] = orig; }
    __syncthreads();
    #pragma unroll
    for (int off = 1; off < 64; off <<= 1) {
        int add = 0;
        if (t < 64 && t >= off) add = sb[t - off];
        __syncthreads();
        if (t < 64) sb[t] += add;
        __syncthreads();
    }
    if (t < 64) sb[t] -= orig;        // inclusive -> exclusive
    __syncthreads();
    int i = blockIdx.x * blockDim.x + t;
    if (i < n) {
        int o = g_offs[i] + sb[i >> 10];    // SCAN_B = 1024
        g_offs[i] = o;
        g_cur[i] = o;
    }
    if (i == n) g_offs[n] = E;
}

__global__ void fill_k(const int* __restrict__ ei, int E) {
    int e = blockIdx.x * blockDim.x + threadIdx.x;
    if (e < E) {
        int d = ei[E + e];
        int pos = atomicAdd(&g_cur[d], 1);
        g_esrc[pos] = ei[e];
    }
}

// ---------------- gather v2: one warp per node, LDG.64 per edge per lane ---------
__global__ void gather_k(const __half2* __restrict__ feat, int N) {
    int gw = (blockIdx.x * blockDim.x + threadIdx.x) >> 5;
    int lane = threadIdx.x & 31;
    if (gw >= N) return;
    int s0 = g_offs[gw], s1 = g_offs[gw + 1];
    const uint2* f = (const uint2*)feat;            // row = 32 uint2 (256B)
    float4 acc = make_float4(0.f, 0.f, 0.f, 0.f);
    int e = s0;
    for (; e + 2 <= s1; e += 2) {
        int a = g_esrc[e], b = g_esrc[e + 1];
        uint2 va = __ldg(f + (size_t)a * 32 + lane);
        uint2 vb = __ldg(f + (size_t)b * 32 + lane);
        float2 fa0 = __half22float2(*(__half2*)&va.x);
        float2 fa1 = __half22float2(*(__half2*)&va.y);
        float2 fb0 = __half22float2(*(__half2*)&vb.x);
        float2 fb1 = __half22float2(*(__half2*)&vb.y);
        acc.x += fa0.x + fb0.x; acc.y += fa0.y + fb0.y;
        acc.z += fa1.x + fb1.x; acc.w += fa1.y + fb1.y;
    }
    if (e < s1) {
        int a = g_esrc[e];
        uint2 va = __ldg(f + (size_t)a * 32 + lane);
        float2 fa0 = __half22float2(*(__half2*)&va.x);
        float2 fa1 = __half22float2(*(__half2*)&va.y);
        acc.x += fa0.x; acc.y += fa0.y; acc.z += fa1.x; acc.w += fa1.y;
    }
    float inv = 1.0f / fmaxf((float)(s1 - s0), 1.0f);
    uint2 o;
    *(__half2*)&o.x = __floats2half2_rn(acc.x * inv, acc.y * inv);
    *(__half2*)&o.y = __floats2half2_rn(acc.z * inv, acc.w * inv);
    ((uint2*)g_agg16)[(size_t)gw * 32 + lane] = o;
}

// ---------------- HMMA node transform ----------------
template<bool OUT_HALF>
__global__ void __launch_bounds__(256, 2)
mma_transform_k(const uint32_t* __restrict__ aggH,   // [m][64] half2-as-u32
                const uint32_t* __restrict__ selfH,
                const uint2* __restrict__ bfrag,     // 8192 x 8B fragments
                const float* __restrict__ bias,
                float* __restrict__ outF, __half2* __restrict__ outH,
                int nNodes, int ntiles) {
    extern __shared__ char smraw[];
    uint2* sB = (uint2*)smraw;                        // 64KB
    float* sBias = (float*)(smraw + 65536);
    int tid = threadIdx.x;
    for (int i = tid; i < 8192; i += 256) sB[i] = __ldg(bfrag + i);
    if (tid < 128) sBias[tid] = __ldg(bias + tid);
    __syncthreads();

    int warp = tid >> 5, lane = tid & 31;
    int r = lane >> 2, c = lane & 3;

    for (int tile = blockIdx.x; tile < ntiles; tile += gridDim.x) {
        int m0 = tile * 128 + warp * 16;
        size_t row0 = (size_t)min(m0 + r,     nNodes - 1);
        size_t row1 = (size_t)min(m0 + r + 8, nNodes - 1);
        const uint32_t* p0a = aggH  + row0 * 64 + c;
        const uint32_t* p1a = aggH  + row1 * 64 + c;
        const uint32_t* p0s = selfH + row0 * 64 + c;
        const uint32_t* p1s = selfH + row1 * 64 + c;

        float acc[16][4];
        #pragma unroll
        for (int nt = 0; nt < 16; nt++)
            #pragma unroll
            for (int q = 0; q < 4; q++) acc[nt][q] = 0.f;

        #pragma unroll
        for (int ks = 0; ks < 16; ks++) {
            const uint32_t* p0 = (ks < 8) ? p0a + ks * 8 : p0s + (ks - 8) * 8;
            const uint32_t* p1 = (ks < 8) ? p1a + ks * 8 : p1s + (ks - 8) * 8;
            uint32_t a0 = __ldg(p0), a2 = __ldg(p0 + 4);
            uint32_t a1 = __ldg(p1), a3 = __ldg(p1 + 4);
            const uint2* bp = sB + ks * 512 + lane;
            #pragma unroll
            for (int nt = 0; nt < 16; nt++) {
                uint2 b = bp[nt * 32];
                mma16816(acc[nt], a0, a1, a2, a3, b.x, b.y);
            }
        }

        bool ok0 = (m0 + r)     < nNodes;
        bool ok1 = (m0 + r + 8) < nNodes;
        #pragma unroll
        for (int nt = 0; nt < 16; nt++) {
            int j = nt * 8 + 2 * c;
            float b0 = sBias[j], b1 = sBias[j + 1];
            float v0 = acc[nt][0] + b0, v1 = acc[nt][1] + b1;
            float v2 = acc[nt][2] + b0, v3 = acc[nt][3] + b1;
            if (OUT_HALF) {
                if (ok0) outH[(size_t)(m0 + r)     * 64 + (j >> 1)] = __floats2half2_rn(v0, v1);
                if (ok1) outH[(size_t)(m0 + r + 8) * 64 + (j >> 1)] = __floats2half2_rn(v2, v3);
            } else {
                if (ok0) *(float2*)(outF + (size_t)(m0 + r)     * 128 + j) = make_float2(v0, v1);
                if (ok1) *(float2*)(outF + (size_t)(m0 + r + 8) * 128 + j) = make_float2(v2, v3);
            }
        }
    }
}

// ---------------- BN stats + finalize (last-block pattern) ----------------
__global__ void stats_k(const float* __restrict__ gamma,
                        const float* __restrict__ beta, float invN, int N) {
    int c2  = threadIdx.x & 63;
    int sub = threadIdx.x >> 6;      // 0..3
    float sx = 0.f, sy = 0.f, qx = 0.f, qy = 0.f;
    for (int row = blockIdx.x * 4 + sub; row < N; row += gridDim.x * 4) {
        float2 f = __half22float2(g_h16[(size_t)row * 64 + c2]);
        sx += f.x; sy += f.y; qx += f.x * f.x; qy += f.y * f.y;
    }
    red_add1(g_colsum   + 2 * c2,     sx);
    red_add1(g_colsum   + 2 * c2 + 1, sy);
    red_add1(g_colsumsq + 2 * c2,     qx);
    red_add1(g_colsumsq + 2 * c2 + 1, qy);
    __threadfence();
    __shared__ int isLast;
    __syncthreads();
    if (threadIdx.x == 0)
        isLast = (atomicAdd(&g_done, 1) == gridDim.x - 1);
    __syncthreads();
    if (isLast && threadIdx.x < 128) {
        int j = threadIdx.x;
        float mu  = __ldcg(g_colsum + j) * invN;
        float var = __ldcg(g_colsumsq + j) * invN - mu * mu;
        float sc  = __ldg(gamma + j) * rsqrtf(var + BN_EPS);
        g_scale[j] = sc;
        g_shift[j] = fmaf(-mu, sc, __ldg(beta + j));
    }
}

// ---------------- relu(bn(h)) in place on fp16 h ----------------
__global__ void relu_bn_k(int total2) {
    int i = blockIdx.x * blockDim.x + threadIdx.x;
    if (i >= total2) return;
    int c2 = i & 63;
    float2 sc = ((const float2*)g_scale)[c2];
    float2 sh = ((const float2*)g_shift)[c2];
    float2 f = __half22float2(g_h16[i]);
    f.x = fmaxf(fmaf(f.x, sc.x, sh.x), 0.f);
    f.y = fmaxf(fmaf(f.y, sc.y, sh.y), 0.f);
    g_h16[i] = __floats2half2_rn(f.x, f.y);
}

// ---------------- launch ----------------
extern "C" void kernel_launch(void* const* d_in, const int* in_sizes, int n_in,
                              void* d_out, int out_size) {
    const float* x     = (const float*)d_in[0];
    const int*   ei    = (const int*)d_in[1];     // int32
    const float* w1l   = (const float*)d_in[2];
    const float* b1l   = (const float*)d_in[3];
    const float* w1r   = (const float*)d_in[4];
    const float* w2l   = (const float*)d_in[5];
    const float* b2l   = (const float*)d_in[6];
    const float* w2r   = (const float*)d_in[7];
    const float* gamma = (const float*)d_in[8];
    const float* beta  = (const float*)d_in[9];
    float*       out   = (float*)d_out;

    int N = in_sizes[0] / D;
    int E = in_sizes[1] / 2;
    int ntiles = (N + 127) / 128;

    void *p_x16, *p_h16, *p_agg16, *p_bf1, *p_bf2;
    cudaGetSymbolAddress(&p_x16,   g_x16);
    cudaGetSymbolAddress(&p_h16,   g_h16);
    cudaGetSymbolAddress(&p_agg16, g_agg16);
    cudaGetSymbolAddress(&p_bf1,   g_bf1);
    cudaGetSymbolAddress(&p_bf2,   g_bf2);

    int smem = 65536 + 512;
    cudaFuncSetAttribute(mma_transform_k<true>,
                         cudaFuncAttributeMaxDynamicSharedMemorySize, smem);
    cudaFuncSetAttribute(mma_transform_k<false>,
                         cudaFuncAttributeMaxDynamicSharedMemorySize, smem);

    // fused setup: zeros (N+257 words) + 64 bfrag blocks + N*32/256 conv blocks
    int zb = (N + 257 + 255) / 256;
    int cb = (N * 32 + 255) / 256;
    setup_k<<<zb + 64 + cb, 256>>>(x, w1l, w1r, w2l, w2r, N, zb);

    // CSR build (reused by both layers)
    int egrid = (E + 255) / 256;
    hist_k<<<egrid, 256>>>(ei, E);
    scan_local_k<<<(N + SCAN_B - 1) / SCAN_B, SCAN_B>>>(N);
    scan_add_k<<<(N + 256) / 256, 256>>>(N, E);
    fill_k<<<egrid, 256>>>(ei, E);

    int ggrid = (N * 32 + 255) / 256;

    // layer 1: h = mean(x_nbr)@W1l + b1 + x@W1r   (fp16 inputs, fp32 acc)
    gather_k<<<ggrid, 256>>>((const __half2*)p_x16, N);
    mma_transform_k<true><<<TGRID, 256, smem>>>(
        (const uint32_t*)p_agg16, (const uint32_t*)p_x16,
        (const uint2*)p_bf1, b1l, nullptr, (__half2*)p_h16, N, ntiles);

    // BN stats + finalize (fused), then relu(bn(h)) in place
    stats_k<<<148, 256>>>(gamma, beta, 1.0f / (float)N, N);
    relu_bn_k<<<(N * 64 + 255) / 256, 256>>>(N * 64);

    // layer 2: out = mean(rbh_nbr)@W2l + b2 + rbh@W2r
    gather_k<<<ggrid, 256>>>((const __half2*)p_h16, N);
    mma_transform_k<false><<<TGRID, 256, smem>>>(
        (const uint32_t*)p_agg16, (const uint32_t*)p_h16,
        (const uint2*)p_bf2, b2l, out, nullptr, N, ntiles);
}